// round 9
// baseline (speedup 1.0000x reference)
#include <cuda_runtime.h>
#include <cuda_fp16.h>
#include <math_constants.h>

#define TPB    256
#define NODES  2049                    // table nodes j in [0, 2048]
#define TMAXF  2048.0f
#define KMAX   1024
#define LOF    (-0.015625f)            // table domain start
#define HSTEP  (33.0f/65536.0f)        // node spacing h (exact in fp32)
#define INVH   (65536.0f/33.0f)        // 1/h
#define TT0    (1024.0f/33.0f)         // -LOF/h
#define MAGICF 12582912.0f             // 1.5 * 2^23
#define GMAX   (148*6)                 // exactly one resident wave

// Device scratch (no allocations allowed)
__device__ float4 g_params[KMAX];      // {mu, s=-0.5*inv_var*log2e, b=log2(coef), 0}
__device__ float2 g_coef[NODES];       // per-node {y0 f32, (c1,c2) half2}
__device__ int    g_interp;            // 1 -> interpolation valid
__device__ float  g_mx, g_tot;         // softmax stats (K>KMAX ultra-fallback)
__device__ unsigned int g_bar = 0;     // monotonic grid-barrier counter (epochs)

__device__ __forceinline__ float ex2(float a) {
    float r;
    asm("ex2.approx.f32 %0, %1;" : "=f"(r) : "f"(a));
    return r;
}

__device__ __forceinline__ float wred_max(float v) {
#pragma unroll
    for (int o = 16; o; o >>= 1) v = fmaxf(v, __shfl_xor_sync(0xffffffffu, v, o));
    return v;
}
__device__ __forceinline__ float wred_min(float v) {
#pragma unroll
    for (int o = 16; o; o >>= 1) v = fminf(v, __shfl_xor_sync(0xffffffffu, v, o));
    return v;
}
__device__ __forceinline__ float wred_sum(float v) {
#pragma unroll
    for (int o = 16; o; o >>= 1) v += __shfl_xor_sync(0xffffffffu, v, o);
    return v;
}

// ---------------------------------------------------------------------------
// Cold fallbacks
// ---------------------------------------------------------------------------
__device__ __noinline__ float direct_eval(float x, int K) {
    float acc = 0.f;
    for (int k = 0; k < K; k++) {
        float4 p = g_params[k];
        float d = x - p.x;
        acc += ex2(fmaf(d * d, p.y, p.z));
    }
    return acc;
}

__device__ __noinline__ float direct_eval_raw(float x, const float* pi_l,
                                              const float* mu, const float* lv, int K) {
    float mx = g_mx, tot = g_tot;
    float acc = 0.f;
    for (int k = 0; k < K; k++) {
        float pi   = expf(pi_l[k] - mx) / tot;
        float l    = lv[k];
        float coef = pi * 0.39894228040143267794f * expf(-0.5f * l);
        float d    = x - mu[k];
        acc += coef * expf(-0.5f * d * d * expf(-l));
    }
    return acc;
}

// ---------------------------------------------------------------------------
// Hot eval: node-centered quadratic, magic-number rounding (no F2I/I2F).
// j = round(t) in [0,2048]; f = t - j in [-0.5, 0.5].
// ---------------------------------------------------------------------------
__device__ __forceinline__ float interp1(float x, const float2* __restrict__ stab) {
    float tt = fmaf(x, INVH, TT0);
    tt = fminf(fmaxf(tt, 0.0f), TMAXF);
    float tb = tt + MAGICF;
    unsigned int j = __float_as_uint(tb) & 0xFFFFu;
    float f = tt - (tb - MAGICF);
    float2 e = stab[j];
    unsigned int u = __float_as_uint(e.y);
    __half2 h12 = *reinterpret_cast<__half2*>(&u);
    float2 c = __half22float2(h12);
    return fmaf(f, fmaf(f, c.y, c.x), e.x);
}

__device__ __forceinline__ float4 interp4(float4 z, const float2* __restrict__ stab) {
    float4 r;
    r.x = interp1(z.x, stab);
    r.y = interp1(z.y, stab);
    r.z = interp1(z.z, stab);
    r.w = interp1(z.w, stab);
    return r;
}

// ---------------------------------------------------------------------------
// Single fused kernel:
//   Phase 1: per-block softmax+params (warp shuffles); warps build their share
//            of table nodes (3-pt stencil, lanes split K) into g_coef.
//   Grid barrier (monotonic epoch counter; grid == one resident wave).
//   Phase 2: load table to smem (aliased over params), interpolate stream.
// ---------------------------------------------------------------------------
__global__ __launch_bounds__(TPB, 6)
void gmm_fused(const float* __restrict__ mz,
               float* __restrict__ out,
               int n, int K,
               const float* __restrict__ pi_l,
               const float* __restrict__ mu,
               const float* __restrict__ lv) {
    __shared__ __align__(16) char smem_raw[NODES * 8 + 8];  // 16.4 KB, aliased
    float4* sp   = reinterpret_cast<float4*>(smem_raw);     // phase 1: params
    float2* stab = reinterpret_cast<float2*>(smem_raw);     // phase 2: table
    __shared__ float sred[8];

    int t   = threadIdx.x;
    int wid = t >> 5, lid = t & 31;
    int kok = (K <= KMAX);

    // ---- softmax max ----
    float m = -CUDART_INF_F;
    for (int k = t; k < K; k += TPB) m = fmaxf(m, pi_l[k]);
    m = wred_max(m);
    if (lid == 0) sred[wid] = m;
    __syncthreads();
    float mx = fmaxf(fmaxf(fmaxf(sred[0], sred[1]), fmaxf(sred[2], sred[3])),
                     fmaxf(fmaxf(sred[4], sred[5]), fmaxf(sred[6], sred[7])));
    __syncthreads();

    // ---- softmax sum ----
    float sum = 0.f;
    for (int k = t; k < K; k += TPB) sum += expf(pi_l[k] - mx);
    sum = wred_sum(sum);
    if (lid == 0) sred[wid] = sum;
    __syncthreads();
    float tot = sred[0] + sred[1] + sred[2] + sred[3]
              + sred[4] + sred[5] + sred[6] + sred[7];
    __syncthreads();

    // ---- params + min log-variance ----
    float lmin = CUDART_INF_F;
    if (kok) {
        for (int k = t; k < K; k += TPB) {
            float pi   = expf(pi_l[k] - mx) / tot;
            float l    = lv[k];
            lmin = fminf(lmin, l);
            float coef = pi * 0.39894228040143267794f * expf(-0.5f * l);
            float s2   = -0.5f * expf(-l) * 1.44269504088896340736f;
            float b    = log2f(fmaxf(coef, 1e-38f));
            sp[k] = make_float4(mu[k], s2, b, 0.f);
        }
    }
    lmin = wred_min(lmin);
    if (lid == 0) sred[wid] = lmin;
    __syncthreads();
    lmin = fminf(fminf(fminf(sred[0], sred[1]), fminf(sred[2], sred[3])),
                 fminf(fminf(sred[4], sred[5]), fminf(sred[6], sred[7])));

    if (blockIdx.x == 0) {
        if (kok) for (int k = t; k < K; k += TPB) g_params[k] = sp[k];
        if (t == 0) {
            float smin = expf(0.5f * lmin);
            g_interp = (kok && smin >= 5.5f * HSTEP) ? 1 : 0;
            g_mx = mx; g_tot = tot;
        }
    }

    // ---- build share: one warp per node, lanes split K ----
    if (kok) {
        int warps_total = gridDim.x * (TPB >> 5);
        for (int node = blockIdx.x * (TPB >> 5) + wid; node < NODES;
             node += warps_total) {
            float x0 = LOF + (float)node * HSTEP;
            float xm = x0 - HSTEP;
            float x1 = x0 + HSTEP;
            float am = 0.f, a0 = 0.f, a1 = 0.f;
            for (int k = lid; k < K; k += 32) {
                float4 pp = sp[k];
                float dm = xm - pp.x;
                float d0 = x0 - pp.x;
                float d1 = x1 - pp.x;
                am += ex2(fmaf(dm * dm, pp.y, pp.z));
                a0 += ex2(fmaf(d0 * d0, pp.y, pp.z));
                a1 += ex2(fmaf(d1 * d1, pp.y, pp.z));
            }
            am = wred_sum(am);
            a0 = wred_sum(a0);
            a1 = wred_sum(a1);
            if (lid == 0) {
                // centered fit: p(f) = y0 + c1 f + c2 f^2, f in [-0.5, 0.5]
                float c1 = 0.5f * (a1 - am);
                float c2 = 0.5f * (am + a1) - a0;
                __half2 h12 = __floats2half2_rn(c1, c2);
                float2 e;
                e.x = a0;
                e.y = __uint_as_float(*reinterpret_cast<unsigned int*>(&h12));
                g_coef[node] = e;
            }
        }
    }

    // ---- grid barrier (all CTAs co-resident: grid <= one wave) ----
    __threadfence();
    __syncthreads();
    if (t == 0) {
        unsigned int ticket = atomicAdd(&g_bar, 1u);
        unsigned int target = (ticket / gridDim.x + 1u) * gridDim.x;
        while (*(volatile unsigned int*)&g_bar < target) __nanosleep(64);
    }
    __syncthreads();
    __threadfence();

    int mode = g_interp;
    int gtid = blockIdx.x * TPB + threadIdx.x;
    int gsz  = gridDim.x * TPB;

    if (mode) {
        // load table into smem (aliases the params buffer; safe post-sync)
        for (int i = threadIdx.x; i < NODES; i += TPB)
            stab[i] = g_coef[i];
        __syncthreads();

        int n4 = n >> 2;
        const float4* mz4 = (const float4*)mz;
        float4* out4 = (float4*)out;

        // MLP=4 batched main loop
        int i = gtid;
        for (; i + 3 * gsz < n4; i += 4 * gsz) {
            float4 z0 = mz4[i];
            float4 z1 = mz4[i + gsz];
            float4 z2 = mz4[i + 2 * gsz];
            float4 z3 = mz4[i + 3 * gsz];
            out4[i]           = interp4(z0, stab);
            out4[i + gsz]     = interp4(z1, stab);
            out4[i + 2 * gsz] = interp4(z2, stab);
            out4[i + 3 * gsz] = interp4(z3, stab);
        }
        for (; i < n4; i += gsz) {
            out4[i] = interp4(mz4[i], stab);
        }
        int rem = n & 3;
        if (gtid < rem) {
            int j = (n4 << 2) + gtid;
            out[j] = interp1(mz[j], stab);
        }
    } else if (K <= KMAX) {
        for (int i = gtid; i < n; i += gsz)
            out[i] = direct_eval(mz[i], K);
    } else {
        for (int i = gtid; i < n; i += gsz)
            out[i] = direct_eval_raw(mz[i], pi_l, mu, lv, K);
    }
}

// ---------------------------------------------------------------------------
// Inputs (metadata order): mz [N], pi_l [K], mu [K], lv [K]. Output: prob [N] f32.
// ---------------------------------------------------------------------------
extern "C" void kernel_launch(void* const* d_in, const int* in_sizes, int n_in,
                              void* d_out, int out_size) {
    const float* mz   = (const float*)d_in[0];
    const float* pi_l = (const float*)d_in[1];
    const float* mu   = (const float*)d_in[2];
    const float* lv   = (const float*)d_in[3];
    float* out = (float*)d_out;
    int n = in_sizes[0];
    int K = in_sizes[1];

    int need = (n / 4 + TPB - 1) / TPB;
    if (need < 1) need = 1;
    int blocks = GMAX;               // exactly one resident wave (6 CTA/SM x 148)
    if (blocks > need) blocks = need;
    gmm_fused<<<blocks, TPB>>>(mz, out, n, K, pi_l, mu, lv);
}

// round 10
// speedup vs baseline: 1.2272x; 1.2272x over previous
#include <cuda_runtime.h>
#include <cuda_fp16.h>
#include <math_constants.h>

#define TPB    256
#define NODES  2049                    // table nodes j in [0, 2048]
#define TMAXF  2048.0f
#define KMAX   1024
#define LOF    (-0.015625f)            // table domain start
#define HSTEP  (33.0f/65536.0f)        // node spacing h (exact in fp32)
#define INVH   (65536.0f/33.0f)        // 1/h
#define TT0    (1024.0f/33.0f)         // -LOF/h
#define MAGICF 12582912.0f             // 1.5 * 2^23
#define BBLD   148                     // builder blocks

// Device scratch (no allocations allowed)
__device__ float4 g_params[KMAX];      // {mu, s=-0.5*inv_var*log2e, b=log2(coef), 0}
__device__ float2 g_coef[NODES];       // per-node {y0 f32, (c1,c2) half2}
__device__ int    g_interp;            // 1 -> interpolation valid
__device__ float  g_mx, g_tot;         // softmax stats (K>KMAX ultra-fallback)

__device__ __forceinline__ float ex2(float a) {
    float r;
    asm("ex2.approx.f32 %0, %1;" : "=f"(r) : "f"(a));
    return r;
}

__device__ __forceinline__ float wred_max(float v) {
#pragma unroll
    for (int o = 16; o; o >>= 1) v = fmaxf(v, __shfl_xor_sync(0xffffffffu, v, o));
    return v;
}
__device__ __forceinline__ float wred_min(float v) {
#pragma unroll
    for (int o = 16; o; o >>= 1) v = fminf(v, __shfl_xor_sync(0xffffffffu, v, o));
    return v;
}
__device__ __forceinline__ float wred_sum(float v) {
#pragma unroll
    for (int o = 16; o; o >>= 1) v += __shfl_xor_sync(0xffffffffu, v, o);
    return v;
}

// ---------------------------------------------------------------------------
// Builder: per-block softmax+params (warp shuffles), then one warp per node
// (3-pt centered stencil, lanes split K) -> packed quadratic coefficients.
// Signals dependent launch after all table writes complete.
// ---------------------------------------------------------------------------
__global__ __launch_bounds__(TPB)
void build_fused(const float* __restrict__ pi_l,
                 const float* __restrict__ mu,
                 const float* __restrict__ lv, int K) {
    __shared__ float4 sp[KMAX];        // 16 KB params
    __shared__ float  sred[8];
    int t   = threadIdx.x;
    int wid = t >> 5, lid = t & 31;
    int kok = (K <= KMAX);

    // ---- softmax max ----
    float m = -CUDART_INF_F;
    for (int k = t; k < K; k += TPB) m = fmaxf(m, pi_l[k]);
    m = wred_max(m);
    if (lid == 0) sred[wid] = m;
    __syncthreads();
    float mx = fmaxf(fmaxf(fmaxf(sred[0], sred[1]), fmaxf(sred[2], sred[3])),
                     fmaxf(fmaxf(sred[4], sred[5]), fmaxf(sred[6], sred[7])));
    __syncthreads();

    // ---- softmax sum ----
    float sum = 0.f;
    for (int k = t; k < K; k += TPB) sum += expf(pi_l[k] - mx);
    sum = wred_sum(sum);
    if (lid == 0) sred[wid] = sum;
    __syncthreads();
    float tot = sred[0] + sred[1] + sred[2] + sred[3]
              + sred[4] + sred[5] + sred[6] + sred[7];
    __syncthreads();

    // ---- params + min log-variance ----
    float lmin = CUDART_INF_F;
    if (kok) {
        for (int k = t; k < K; k += TPB) {
            float pi   = expf(pi_l[k] - mx) / tot;
            float l    = lv[k];
            lmin = fminf(lmin, l);
            float coef = pi * 0.39894228040143267794f * expf(-0.5f * l);
            float s2   = -0.5f * expf(-l) * 1.44269504088896340736f;
            float b    = log2f(fmaxf(coef, 1e-38f));
            sp[k] = make_float4(mu[k], s2, b, 0.f);
        }
    }
    lmin = wred_min(lmin);
    if (lid == 0) sred[wid] = lmin;
    __syncthreads();
    lmin = fminf(fminf(fminf(sred[0], sred[1]), fminf(sred[2], sred[3])),
                 fminf(fminf(sred[4], sred[5]), fminf(sred[6], sred[7])));

    if (blockIdx.x == 0) {
        if (kok) for (int k = t; k < K; k += TPB) g_params[k] = sp[k];
        if (t == 0) {
            // quadratic-interp err ~ (h/sigma)^3 scale; sigma >= 5.5h -> ~1e-4
            float smin = expf(0.5f * lmin);
            g_interp = (kok && smin >= 5.5f * HSTEP) ? 1 : 0;
            g_mx = mx; g_tot = tot;
        }
    }

    // ---- one warp per node: centered 3-pt stencil, lanes split K ----
    if (kok) {
        int warps_total = gridDim.x * (TPB >> 5);
        for (int node = blockIdx.x * (TPB >> 5) + wid; node < NODES;
             node += warps_total) {
            float x0 = LOF + (float)node * HSTEP;
            float xm = x0 - HSTEP;
            float x1 = x0 + HSTEP;
            float am = 0.f, a0 = 0.f, a1 = 0.f;
            for (int k = lid; k < K; k += 32) {
                float4 pp = sp[k];
                float dm = xm - pp.x;
                float d0 = x0 - pp.x;
                float d1 = x1 - pp.x;
                am += ex2(fmaf(dm * dm, pp.y, pp.z));
                a0 += ex2(fmaf(d0 * d0, pp.y, pp.z));
                a1 += ex2(fmaf(d1 * d1, pp.y, pp.z));
            }
            am = wred_sum(am);
            a0 = wred_sum(a0);
            a1 = wred_sum(a1);
            if (lid == 0) {
                // centered fit: p(f) = y0 + c1 f + c2 f^2, f in [-0.5, 0.5]
                float c1 = 0.5f * (a1 - am);
                float c2 = 0.5f * (am + a1) - a0;
                __half2 h12 = __floats2half2_rn(c1, c2);
                float2 e;
                e.x = a0;
                e.y = __uint_as_float(*reinterpret_cast<unsigned int*>(&h12));
                g_coef[node] = e;
            }
        }
    }

    // All table/flag writes done -> allow the dependent kernel to proceed.
    asm volatile("griddepcontrol.launch_dependents;");
}

// ---------------------------------------------------------------------------
// Cold fallbacks
// ---------------------------------------------------------------------------
__device__ __noinline__ float direct_eval(float x, int K) {
    float acc = 0.f;
    for (int k = 0; k < K; k++) {
        float4 p = g_params[k];
        float d = x - p.x;
        acc += ex2(fmaf(d * d, p.y, p.z));
    }
    return acc;
}

__device__ __noinline__ float direct_eval_raw(float x, const float* pi_l,
                                              const float* mu, const float* lv, int K) {
    float mx = g_mx, tot = g_tot;
    float acc = 0.f;
    for (int k = 0; k < K; k++) {
        float pi   = expf(pi_l[k] - mx) / tot;
        float l    = lv[k];
        float coef = pi * 0.39894228040143267794f * expf(-0.5f * l);
        float d    = x - mu[k];
        acc += coef * expf(-0.5f * d * d * expf(-l));
    }
    return acc;
}

// ---------------------------------------------------------------------------
// Hot eval: node-centered quadratic, magic-number rounding (no F2I/I2F).
// j = round(t) in [0,2048]; f = t - j in [-0.5, 0.5].
// ---------------------------------------------------------------------------
__device__ __forceinline__ float interp1(float x, const float2* __restrict__ stab) {
    float tt = fmaf(x, INVH, TT0);
    tt = fminf(fmaxf(tt, 0.0f), TMAXF);
    float tb = tt + MAGICF;
    unsigned int j = __float_as_uint(tb) & 0xFFFFu;
    float f = tt - (tb - MAGICF);
    float2 e = stab[j];
    unsigned int u = __float_as_uint(e.y);
    __half2 h12 = *reinterpret_cast<__half2*>(&u);
    float2 c = __half22float2(h12);
    return fmaf(f, fmaf(f, c.y, c.x), e.x);
}

__device__ __forceinline__ float4 interp4(float4 z, const float2* __restrict__ stab) {
    float4 r;
    r.x = interp1(z.x, stab);
    r.y = interp1(z.y, stab);
    r.z = interp1(z.z, stab);
    r.w = interp1(z.w, stab);
    return r;
}

__global__ __launch_bounds__(TPB, 6)
void interp_kernel(const float* __restrict__ mz,
                   float* __restrict__ out,
                   int n, int K,
                   const float* __restrict__ pi_l,
                   const float* __restrict__ mu,
                   const float* __restrict__ lv) {
    __shared__ float2 stab[NODES];       // 16.4 KB

    int gtid = blockIdx.x * TPB + threadIdx.x;
    int gsz  = gridDim.x * TPB;
    int n4   = n >> 2;
    const float4* mz4 = (const float4*)mz;
    float4* out4 = (float4*)out;

    // --- Prologue (independent of builder): prefetch first MLP-4 batch ---
    float4 z0, z1, z2, z3;
    int i = gtid;
    bool pre = (i + 3 * gsz < n4);
    if (pre) {
        z0 = mz4[i];
        z1 = mz4[i + gsz];
        z2 = mz4[i + 2 * gsz];
        z3 = mz4[i + 3 * gsz];
    }

    // --- Wait for builder's results to be visible ---
    asm volatile("griddepcontrol.wait;" ::: "memory");

    int mode = g_interp;                 // uniform across grid
    if (mode) {
#pragma unroll 4
        for (int k = threadIdx.x; k < NODES; k += TPB)
            stab[k] = g_coef[k];
        __syncthreads();

        if (pre) {
            out4[i]           = interp4(z0, stab);
            out4[i + gsz]     = interp4(z1, stab);
            out4[i + 2 * gsz] = interp4(z2, stab);
            out4[i + 3 * gsz] = interp4(z3, stab);
            i += 4 * gsz;
        }
        for (; i + 3 * gsz < n4; i += 4 * gsz) {
            float4 y0 = mz4[i];
            float4 y1 = mz4[i + gsz];
            float4 y2 = mz4[i + 2 * gsz];
            float4 y3 = mz4[i + 3 * gsz];
            out4[i]           = interp4(y0, stab);
            out4[i + gsz]     = interp4(y1, stab);
            out4[i + 2 * gsz] = interp4(y2, stab);
            out4[i + 3 * gsz] = interp4(y3, stab);
        }
        for (; i < n4; i += gsz) {
            out4[i] = interp4(mz4[i], stab);
        }
        int rem = n & 3;
        if (gtid < rem) {
            int j = (n4 << 2) + gtid;
            out[j] = interp1(mz[j], stab);
        }
    } else if (K <= KMAX) {
        for (int k = gtid; k < n; k += gsz)
            out[k] = direct_eval(mz[k], K);
    } else {
        for (int k = gtid; k < n; k += gsz)
            out[k] = direct_eval_raw(mz[k], pi_l, mu, lv, K);
    }
}

// ---------------------------------------------------------------------------
// Inputs (metadata order): mz [N], pi_l [K], mu [K], lv [K]. Output: prob [N] f32.
// ---------------------------------------------------------------------------
extern "C" void kernel_launch(void* const* d_in, const int* in_sizes, int n_in,
                              void* d_out, int out_size) {
    const float* mz   = (const float*)d_in[0];
    const float* pi_l = (const float*)d_in[1];
    const float* mu   = (const float*)d_in[2];
    const float* lv   = (const float*)d_in[3];
    float* out = (float*)d_out;
    int n = in_sizes[0];
    int K = in_sizes[1];

    build_fused<<<BBLD, TPB>>>(pi_l, mu, lv, K);

    int need = (n / 4 + TPB - 1) / TPB;
    if (need < 1) need = 1;
    int blocks = 148 * 6;                      // one resident wave at 6 CTA/SM
    if (blocks > need) blocks = need;

    // Programmatic dependent launch: interp starts early, overlapping the
    // builder; griddepcontrol.wait inside gates on the builder's writes.
    cudaLaunchConfig_t cfg = {};
    cfg.gridDim  = dim3((unsigned)blocks, 1, 1);
    cfg.blockDim = dim3(TPB, 1, 1);
    cfg.dynamicSmemBytes = 0;
    cfg.stream = 0;
    cudaLaunchAttribute attrs[1];
    attrs[0].id = cudaLaunchAttributeProgrammaticStreamSerialization;
    attrs[0].val.programmaticStreamSerializationAllowed = 1;
    cfg.attrs = attrs;
    cfg.numAttrs = 1;
    cudaLaunchKernelEx(&cfg, interp_kernel, mz, out, n, K, pi_l, mu, lv);
}